// round 2
// baseline (speedup 1.0000x reference)
#include <cuda_runtime.h>
#include <cstdint>

#define TSTEPS  1024
#define FEAT    64
#define UNITS   256
#define FOURU   1024
#define KDIM    320      // 64 (W rows) + 256 (Uh rows)
#define NCOLS   128      // gate-columns per CTA: 32 units x 4 gates
#define ASTR    36       // padded floats per a_t row (16B aligned, bank-spread)
#define CLUSTER 8
#define THREADS 128
#define BB      32       // batch rows per cluster
#define NCLUST  16

// ---------- packed f32x2 helpers (Blackwell FFMA2 path) ----------
__device__ __forceinline__ unsigned long long pk2(float lo, float hi) {
    unsigned long long r;
    asm("mov.b64 %0, {%1, %2};" : "=l"(r) : "f"(lo), "f"(hi));
    return r;
}
__device__ __forceinline__ void fma2(unsigned long long& d,
                                     unsigned long long a,
                                     unsigned long long b) {
    asm("fma.rn.f32x2 %0, %1, %2, %0;" : "+l"(d) : "l"(a), "l"(b));
}
__device__ __forceinline__ float2 up2(unsigned long long v) {
    float2 r;
    asm("mov.b64 {%0, %1}, %2;" : "=f"(r.x), "=f"(r.y) : "l"(v));
    return r;
}

// ---------- fast-but-accurate-enough activations (~2 ulp via ex2/rcp MUFU) ----------
__device__ __forceinline__ float fsig(float x) {
    return __fdividef(1.0f, 1.0f + __expf(-x));
}
__device__ __forceinline__ float ftanh(float x) {
    return fmaf(2.0f, fsig(2.0f * x), -1.0f);
}

// Persistent cluster kernel: each 8-CTA cluster owns 32 batch rows; each CTA
// owns 32 hidden units (128 gate cols) with its [W;Uh] slice resident in SMEM.
// Per step: z = a @ Uc (f32x2 FFMA), gates, h broadcast via DSMEM to all 8
// a-buffers, 2 cluster barriers. Epilogue: out[b,:] = sigmoid(h_T[b]·dw + db).
extern "C" __global__ void __launch_bounds__(THREADS, 1) __cluster_dims__(CLUSTER, 1, 1)
lstm_attn_kernel(const float* __restrict__ x,  const float* __restrict__ W,
                 const float* __restrict__ Uh, const float* __restrict__ bias,
                 const float* __restrict__ dw, const float* __restrict__ db,
                 float* __restrict__ out)
{
    extern __shared__ float smem[];
    float* Uc  = smem;                    // [KDIM][NCOLS]   163840 B
    float* at  = smem + KDIM * NCOLS;     // [KDIM][ASTR]     46080 B  (a = [x_t ; h])
    float* bsm = at + KDIM * ASTR;        // [NCOLS]            512 B

    const int tid = threadIdx.x;
    uint32_t rank, cid;
    asm("mov.u32 %0, %%cluster_ctarank;" : "=r"(rank));
    asm("mov.u32 %0, %%clusterid.x;"     : "=r"(cid));

    // ---- one-time: load this CTA's weight slice (col = unit*4 + gate) ----
    {
        const int c    = tid;              // THREADS == NCOLS
        const int unit = c >> 2;
        const int gate = c & 3;
        const int gcol = gate * UNITS + (int)rank * 32 + unit;
        bsm[c] = bias[gcol];
        for (int k = 0; k < FEAT; k++)
            Uc[k * NCOLS + c] = W[(size_t)k * FOURU + gcol];
        for (int k = 0; k < UNITS; k++)
            Uc[(FEAT + k) * NCOLS + c] = Uh[(size_t)k * FOURU + gcol];
    }
    // zero the h region of a (rows 64..319)
    for (int i = tid; i < UNITS * ASTR; i += THREADS)
        at[FEAT * ASTR + i] = 0.0f;
    __syncthreads();

    const int bq = tid >> 5;   // warp id: batch group (8 batches)
    const int cq = tid & 31;   // lane: unit within CTA

    float b4[4];
    #pragma unroll
    for (int g = 0; g < 4; g++) b4[g] = bsm[cq * 4 + g];

    const float* xb = x + (size_t)cid * BB * TSTEPS * FEAT;

    float cst[8];
    #pragma unroll
    for (int j = 0; j < 8; j++) cst[j] = 0.0f;

    // shared::cluster u32 address of my h destination row segment
    uint32_t at_u32;
    asm("{ .reg .u64 t0; cvta.to.shared.u64 t0, %1; cvt.u32.u64 %0, t0; }"
        : "=r"(at_u32) : "l"(at));
    const uint32_t hdst = at_u32 +
        (uint32_t)(((FEAT + (int)rank * 32 + cq) * ASTR + bq * 8) * 4);

    for (int t = 0; t < TSTEPS; t++) {
        // ---- stage x_t into a rows [0,64): a[f][b] = x[b,t,f] ----
        #pragma unroll
        for (int i = 0; i < 4; i++) {
            const int idx = tid + i * THREADS;      // 0..511
            const int b   = idx >> 4;               // 0..31
            const int fq  = idx & 15;               // float4 index
            const float4 v = *reinterpret_cast<const float4*>(
                xb + ((size_t)b * TSTEPS + t) * FEAT + fq * 4);
            const int r0 = fq * 4;
            at[(r0 + 0) * ASTR + b] = v.x;
            at[(r0 + 1) * ASTR + b] = v.y;
            at[(r0 + 2) * ASTR + b] = v.z;
            at[(r0 + 3) * ASTR + b] = v.w;
        }
        __syncthreads();

        // ---- z = a @ Uc  (thread: 8 batches x 4 gate-cols, f32x2 packed) ----
        unsigned long long acc[4][4];
        #pragma unroll
        for (int p = 0; p < 4; p++)
            #pragma unroll
            for (int g = 0; g < 4; g++)
                acc[p][g] = pk2(b4[g], b4[g]);

        const float* ucp = Uc + cq * 4;
        const float* ap  = at + bq * 8;
        #pragma unroll 4
        for (int k = 0; k < KDIM; k++) {
            const float4 u4 = *reinterpret_cast<const float4*>(ucp + k * NCOLS);
            const float4 a0 = *reinterpret_cast<const float4*>(ap + k * ASTR);
            const float4 a1 = *reinterpret_cast<const float4*>(ap + k * ASTR + 4);
            unsigned long long ug[4] = { pk2(u4.x, u4.x), pk2(u4.y, u4.y),
                                         pk2(u4.z, u4.z), pk2(u4.w, u4.w) };
            unsigned long long apair[4] = { pk2(a0.x, a0.y), pk2(a0.z, a0.w),
                                            pk2(a1.x, a1.y), pk2(a1.z, a1.w) };
            #pragma unroll
            for (int p = 0; p < 4; p++)
                #pragma unroll
                for (int g = 0; g < 4; g++)
                    fma2(acc[p][g], apair[p], ug[g]);
        }

        // all cluster CTAs must finish READING a before anyone overwrites h
        asm volatile("barrier.cluster.arrive.aligned;" ::: "memory");

        // ---- gates + state update (registers only; overlaps barrier skew) ----
        float hh[8];
        #pragma unroll
        for (int p = 0; p < 4; p++) {
            const float2 zi = up2(acc[p][0]);
            const float2 zf = up2(acc[p][1]);
            const float2 zg = up2(acc[p][2]);
            const float2 zo = up2(acc[p][3]);
            {
                const int j = 2 * p;
                const float ig = fsig(zi.x), fg = fsig(zf.x);
                const float gg = ftanh(zg.x), og = fsig(zo.x);
                const float cn = fmaf(fg, cst[j], ig * gg);
                cst[j] = cn;
                hh[j]  = og * ftanh(cn);
            }
            {
                const int j = 2 * p + 1;
                const float ig = fsig(zi.y), fg = fsig(zf.y);
                const float gg = ftanh(zg.y), og = fsig(zo.y);
                const float cn = fmaf(fg, cst[j], ig * gg);
                cst[j] = cn;
                hh[j]  = og * ftanh(cn);
            }
        }

        asm volatile("barrier.cluster.wait.aligned;" ::: "memory");

        // ---- broadcast my h chunk (unit cq, batches bq*8..+7) to all 8 CTAs ----
        #pragma unroll
        for (int r = 0; r < CLUSTER; r++) {
            uint32_t ra;
            asm("mapa.shared::cluster.u32 %0, %1, %2;" : "=r"(ra) : "r"(hdst), "r"(r));
            asm volatile("st.shared::cluster.v4.b32 [%0], {%1,%2,%3,%4};" ::
                "r"(ra),
                "r"(__float_as_uint(hh[0])), "r"(__float_as_uint(hh[1])),
                "r"(__float_as_uint(hh[2])), "r"(__float_as_uint(hh[3])) : "memory");
            asm volatile("st.shared::cluster.v4.b32 [%0+16], {%1,%2,%3,%4};" ::
                "r"(ra),
                "r"(__float_as_uint(hh[4])), "r"(__float_as_uint(hh[5])),
                "r"(__float_as_uint(hh[6])), "r"(__float_as_uint(hh[7])) : "memory");
        }

        // h writes must be visible cluster-wide before next step's GEMM
        asm volatile("barrier.cluster.arrive.aligned;" ::: "memory");
        asm volatile("barrier.cluster.wait.aligned;"   ::: "memory");
    }

    // ---- epilogue: a rows [64,320) now hold full h_T for this cluster ----
    // out[b, t] = sigmoid(h_T[b] . dw + db)  for all t  (softmax over size-1 axis == 1)
    {
        const int bl = (int)rank * 4 + bq;   // this CTA covers 4 of 32 batch rows
        float s = 0.0f;
        for (int u = cq; u < UNITS; u += 32)
            s += at[(FEAT + u) * ASTR + bl] * dw[u];
        #pragma unroll
        for (int o = 16; o > 0; o >>= 1)
            s += __shfl_xor_sync(0xffffffffu, s, o);
        const float val = fsig(s + db[0]);
        float* op = out + ((size_t)cid * BB + bl) * TSTEPS;
        for (int i = cq; i < TSTEPS; i += 32)
            op[i] = val;
    }
}

extern "C" void kernel_launch(void* const* d_in, const int* in_sizes, int n_in,
                              void* d_out, int out_size)
{
    const float* x  = (const float*)d_in[0];
    const float* W  = (const float*)d_in[1];
    const float* Uh = (const float*)d_in[2];
    const float* b  = (const float*)d_in[3];
    const float* dw = (const float*)d_in[4];
    const float* db = (const float*)d_in[5];
    float* out = (float*)d_out;

    const size_t smem = (size_t)(KDIM * NCOLS + KDIM * ASTR + NCOLS) * sizeof(float);
    cudaFuncSetAttribute(lstm_attn_kernel,
                         cudaFuncAttributeMaxDynamicSharedMemorySize, (int)smem);
    lstm_attn_kernel<<<NCLUST * CLUSTER, THREADS, smem>>>(x, W, Uh, b, dw, db, out);
}